// round 4
// baseline (speedup 1.0000x reference)
#include <cuda_runtime.h>
#include <math.h>

// Shapes (fixed by the problem)
#define Bn 2
#define Tn 2048
#define Cn 1024
#define Hn 16
#define Dn 64
#define Mn (Bn * Tn)          // 4096 rows for all projections

// ---------------------------------------------------------------------------
// Scratch (device globals — no allocation allowed)
// ---------------------------------------------------------------------------
__device__ float g_q[(size_t)Bn * Hn * Tn * Dn];   // (B,H,T,D)
__device__ float g_k[(size_t)Bn * Hn * Tn * Dn];
__device__ float g_v[(size_t)Bn * Hn * Tn * Dn];
__device__ float g_y[(size_t)Bn * Tn * Cn];        // attn out, then GN'd in place
__device__ float g_ptab[Hn * Tn];                  // 0.125 * gamma_h^k

// ---------------------------------------------------------------------------
// Decay table: ptab[h][k] = (1/sqrt(D)) * gamma_h^k, gamma_h = 1 - 2^(-5-h/2)
// Built in fp64 so the k=2047 tail keeps full fp32 accuracy. Idempotent.
// ---------------------------------------------------------------------------
__global__ void init_ptab_kernel() {
    int h = blockIdx.x;
    double gamma = 1.0 - exp2(-5.0 - 0.5 * (double)h);
    double l2g = log2(gamma);
    for (int k = threadIdx.x; k < Tn; k += blockDim.x) {
        g_ptab[h * Tn + k] = (float)(0.125 * exp2(l2g * (double)k));
    }
}

// ---------------------------------------------------------------------------
// GEMM core: C[m,n] = sum_k A[m,k] * W[n,k]   (A: Mx1024 row-major, W: 1024x1024)
// BM=128, BN=64, BK=16, 256 threads, 8x4 microtile. Smem staged k-major so the
// inner loop reads are broadcast (a-frag) / 2-way (b-frag).
// ---------------------------------------------------------------------------
struct GemmFrag {
    float acc[8][4];
};

__device__ __forceinline__ void gemm_body(const float* __restrict__ A,
                                          const float* __restrict__ W,
                                          int m0, int n0, GemmFrag& f) {
    __shared__ float As[16][128];
    __shared__ float Bs[16][64];
    const int tid = threadIdx.x;
    const int tx = tid & 15, ty = tid >> 4;
    const int row0 = ty * 8, col0 = tx * 4;

#pragma unroll
    for (int i = 0; i < 8; i++)
#pragma unroll
        for (int j = 0; j < 4; j++) f.acc[i][j] = 0.f;

    const int ar = tid >> 2;      // 0..63
    const int ac4 = tid & 3;      // 0..3 (float4 index along k)

    for (int k0 = 0; k0 < Cn; k0 += 16) {
        // A tile: 128x16 (2 float4 per thread), stored transposed As[k][m]
#pragma unroll
        for (int l = 0; l < 2; l++) {
            int r = ar + l * 64;
            float4 v = *(const float4*)(A + (size_t)(m0 + r) * Cn + k0 + ac4 * 4);
            As[ac4 * 4 + 0][r] = v.x;
            As[ac4 * 4 + 1][r] = v.y;
            As[ac4 * 4 + 2][r] = v.z;
            As[ac4 * 4 + 3][r] = v.w;
        }
        // W tile: 64x16 (1 float4 per thread), stored transposed Bs[k][n]
        {
            float4 v = *(const float4*)(W + (size_t)(n0 + ar) * Cn + k0 + ac4 * 4);
            Bs[ac4 * 4 + 0][ar] = v.x;
            Bs[ac4 * 4 + 1][ar] = v.y;
            Bs[ac4 * 4 + 2][ar] = v.z;
            Bs[ac4 * 4 + 3][ar] = v.w;
        }
        __syncthreads();
#pragma unroll
        for (int kk = 0; kk < 16; kk++) {
            float a[8], b[4];
            *(float4*)&a[0] = *(const float4*)&As[kk][row0];
            *(float4*)&a[4] = *(const float4*)&As[kk][row0 + 4];
            *(float4*)&b[0] = *(const float4*)&Bs[kk][col0];
#pragma unroll
            for (int i = 0; i < 8; i++)
#pragma unroll
                for (int j = 0; j < 4; j++)
                    f.acc[i][j] = fmaf(a[i], b[j], f.acc[i][j]);
        }
        __syncthreads();
    }
}

// QKV projection: grid (16 n-tiles, 32 m-tiles, 3 weights). BN==Dn so each
// n-tile is exactly one head; epilogue scatters into (B,H,T,D).
__global__ __launch_bounds__(256) void gemm_qkv_kernel(const float* __restrict__ x,
                                                       const float* __restrict__ Wq,
                                                       const float* __restrict__ Wk,
                                                       const float* __restrict__ Wv) {
    const int z = blockIdx.z;
    const float* __restrict__ W = (z == 0) ? Wq : (z == 1) ? Wk : Wv;
    float* out = (z == 0) ? g_q : (z == 1) ? g_k : g_v;

    const int m0 = blockIdx.y * 128;
    const int n0 = blockIdx.x * 64;
    GemmFrag f;
    gemm_body(x, W, m0, n0, f);

    const int tid = threadIdx.x;
    const int tx = tid & 15, ty = tid >> 4;
    const int row0 = ty * 8, col0 = tx * 4;
    const int h = blockIdx.x;   // BN == Dn
#pragma unroll
    for (int i = 0; i < 8; i++) {
        int m = m0 + row0 + i;
        int b = m >> 11;            // T = 2048
        int t = m & (Tn - 1);
        float4 v = make_float4(f.acc[i][0], f.acc[i][1], f.acc[i][2], f.acc[i][3]);
        *(float4*)(out + ((size_t)(b * Hn + h) * Tn + t) * Dn + col0) = v;
    }
}

// Output projection: reads GN'd g_y, writes plain (B*T, C).
__global__ __launch_bounds__(256) void gemm_out_kernel(const float* __restrict__ Wo,
                                                       float* __restrict__ outp) {
    const int m0 = blockIdx.y * 128;
    const int n0 = blockIdx.x * 64;
    GemmFrag f;
    gemm_body(g_y, Wo, m0, n0, f);

    const int tid = threadIdx.x;
    const int tx = tid & 15, ty = tid >> 4;
    const int row0 = ty * 8, col0 = tx * 4;
#pragma unroll
    for (int i = 0; i < 8; i++) {
        int m = m0 + row0 + i;
        float4 v = make_float4(f.acc[i][0], f.acc[i][1], f.acc[i][2], f.acc[i][3]);
        *(float4*)(outp + (size_t)m * Cn + n0 + col0) = v;
    }
}

// ---------------------------------------------------------------------------
// Retention attention. One block per (b*h, query-tile of 64). Flash-style
// sweep over causal key tiles. S reuses K's smem (sync-separated) so the
// whole kernel fits in 48KB static smem. K is stored transposed with an XOR
// swizzle col = j ^ (d & 60) to keep the transpose store ~2-way conflicted.
// ---------------------------------------------------------------------------
__global__ __launch_bounds__(256) void retention_kernel() {
    __shared__ float Qs[64 * 64];     // natural [i][d]
    __shared__ float KSs[64 * 64];    // K transposed+swizzled, then aliased as S [i][j]
    __shared__ float Vs[64 * 64];     // natural [j][d]

    const int bh = blockIdx.y;
    const int h = bh & (Hn - 1);
    const int b = bh >> 4;
    const int qt = (int)gridDim.x - 1 - (int)blockIdx.x;   // heavy tiles first
    const int qbase = qt * 64;

    const float* __restrict__ Qg = g_q + (size_t)bh * Tn * Dn;
    const float* __restrict__ Kg = g_k + (size_t)bh * Tn * Dn;
    const float* __restrict__ Vg = g_v + (size_t)bh * Tn * Dn;
    const float* __restrict__ pt = g_ptab + h * Tn;

    const int tid = threadIdx.x;
    const int tx = tid & 15, ty = tid >> 4;
    const int i0 = ty * 4, j0 = tx * 4;

    // Load Q tile (natural layout, coalesced float4)
#pragma unroll
    for (int l = 0; l < 4; l++) {
        int f4 = tid + l * 256;
        int r = f4 >> 4, c4 = f4 & 15;
        *(float4*)&Qs[r * 64 + c4 * 4] =
            *(const float4*)(Qg + (size_t)(qbase + r) * Dn + c4 * 4);
    }

    float oacc[4][4];
#pragma unroll
    for (int a = 0; a < 4; a++)
#pragma unroll
        for (int c = 0; c < 4; c++) oacc[a][c] = 0.f;

    for (int kt = 0; kt <= qt; kt++) {
        const int kbase = kt * 64;
        __syncthreads();   // prior O-gemm reads of KSs/Vs done (and Q load at kt==0)

        // Load K (transposed + swizzled) and V (natural)
#pragma unroll
        for (int l = 0; l < 4; l++) {
            int f4 = tid + l * 256;
            int r = f4 >> 4, c4 = f4 & 15;
            float4 kv = *(const float4*)(Kg + (size_t)(kbase + r) * Dn + c4 * 4);
            int d0 = c4 * 4;
            KSs[(d0 + 0) * 64 + (r ^ ((d0 + 0) & 60))] = kv.x;
            KSs[(d0 + 1) * 64 + (r ^ ((d0 + 1) & 60))] = kv.y;
            KSs[(d0 + 2) * 64 + (r ^ ((d0 + 2) & 60))] = kv.z;
            KSs[(d0 + 3) * 64 + (r ^ ((d0 + 3) & 60))] = kv.w;
            *(float4*)&Vs[r * 64 + c4 * 4] =
                *(const float4*)(Vg + (size_t)(kbase + r) * Dn + c4 * 4);
        }
        __syncthreads();

        // S = Q K^T  (4x4 fragment per thread)
        float sacc[4][4];
#pragma unroll
        for (int a = 0; a < 4; a++)
#pragma unroll
            for (int c = 0; c < 4; c++) sacc[a][c] = 0.f;

#pragma unroll 16
        for (int d = 0; d < 64; d++) {
            float q0 = Qs[(i0 + 0) * 64 + d];
            float q1 = Qs[(i0 + 1) * 64 + d];
            float q2 = Qs[(i0 + 2) * 64 + d];
            float q3 = Qs[(i0 + 3) * 64 + d];
            float4 kk = *(const float4*)&KSs[d * 64 + (j0 ^ (d & 60))];
            sacc[0][0] = fmaf(q0, kk.x, sacc[0][0]); sacc[0][1] = fmaf(q0, kk.y, sacc[0][1]);
            sacc[0][2] = fmaf(q0, kk.z, sacc[0][2]); sacc[0][3] = fmaf(q0, kk.w, sacc[0][3]);
            sacc[1][0] = fmaf(q1, kk.x, sacc[1][0]); sacc[1][1] = fmaf(q1, kk.y, sacc[1][1]);
            sacc[1][2] = fmaf(q1, kk.z, sacc[1][2]); sacc[1][3] = fmaf(q1, kk.w, sacc[1][3]);
            sacc[2][0] = fmaf(q2, kk.x, sacc[2][0]); sacc[2][1] = fmaf(q2, kk.y, sacc[2][1]);
            sacc[2][2] = fmaf(q2, kk.z, sacc[2][2]); sacc[2][3] = fmaf(q2, kk.w, sacc[2][3]);
            sacc[3][0] = fmaf(q3, kk.x, sacc[3][0]); sacc[3][1] = fmaf(q3, kk.y, sacc[3][1]);
            sacc[3][2] = fmaf(q3, kk.z, sacc[3][2]); sacc[3][3] = fmaf(q3, kk.w, sacc[3][3]);
        }

        // Decay mask * scale: diff = (qbase+i0+a) - (kbase+j0+b); only 7 distinct
        // per fragment. Negative diffs fetch a literal 0 (causal zero).
        {
            const int dbase = qbase + i0 - kbase - j0;
            float pv[7];
#pragma unroll
            for (int e = 0; e < 7; e++) {
                int dd = dbase - 3 + e;
                pv[e] = (dd >= 0) ? pt[dd] : 0.f;
            }
#pragma unroll
            for (int a = 0; a < 4; a++)
#pragma unroll
                for (int c = 0; c < 4; c++)
                    sacc[a][c] *= pv[a - c + 3];
        }

        __syncthreads();   // everyone done reading KSs as K
        // Store S (natural [i][j]) into the K region
        float* Ss = KSs;
#pragma unroll
        for (int a = 0; a < 4; a++) {
            *(float4*)&Ss[(i0 + a) * 64 + j0] =
                make_float4(sacc[a][0], sacc[a][1], sacc[a][2], sacc[a][3]);
        }
        __syncthreads();

        // O += S @ V
#pragma unroll 16
        for (int j = 0; j < 64; j++) {
            float s0 = Ss[(i0 + 0) * 64 + j];
            float s1 = Ss[(i0 + 1) * 64 + j];
            float s2 = Ss[(i0 + 2) * 64 + j];
            float s3 = Ss[(i0 + 3) * 64 + j];
            float4 vv = *(const float4*)&Vs[j * 64 + j0];
            oacc[0][0] = fmaf(s0, vv.x, oacc[0][0]); oacc[0][1] = fmaf(s0, vv.y, oacc[0][1]);
            oacc[0][2] = fmaf(s0, vv.z, oacc[0][2]); oacc[0][3] = fmaf(s0, vv.w, oacc[0][3]);
            oacc[1][0] = fmaf(s1, vv.x, oacc[1][0]); oacc[1][1] = fmaf(s1, vv.y, oacc[1][1]);
            oacc[1][2] = fmaf(s1, vv.z, oacc[1][2]); oacc[1][3] = fmaf(s1, vv.w, oacc[1][3]);
            oacc[2][0] = fmaf(s2, vv.x, oacc[2][0]); oacc[2][1] = fmaf(s2, vv.y, oacc[2][1]);
            oacc[2][2] = fmaf(s2, vv.z, oacc[2][2]); oacc[2][3] = fmaf(s2, vv.w, oacc[2][3]);
            oacc[3][0] = fmaf(s3, vv.x, oacc[3][0]); oacc[3][1] = fmaf(s3, vv.y, oacc[3][1]);
            oacc[3][2] = fmaf(s3, vv.z, oacc[3][2]); oacc[3][3] = fmaf(s3, vv.w, oacc[3][3]);
        }
    }

    // Write merged-head output y[b, t, h*64 + d]
#pragma unroll
    for (int a = 0; a < 4; a++) {
        int t = qbase + i0 + a;
        *(float4*)(g_y + ((size_t)b * Tn + t) * Cn + h * Dn + j0) =
            make_float4(oacc[a][0], oacc[a][1], oacc[a][2], oacc[a][3]);
    }
}

// ---------------------------------------------------------------------------
// GroupNorm over (D, T) per (b, h), in place on g_y. Two-pass for a stable
// variance. Each thread owns a fixed 4-channel slice so gn_w/gn_b load once.
// ---------------------------------------------------------------------------
__global__ __launch_bounds__(256) void groupnorm_kernel(const float* __restrict__ gn_w,
                                                        const float* __restrict__ gn_b) {
    __shared__ float red[256];
    __shared__ float s_mu, s_rstd;
    const int bh = blockIdx.x;
    const int b = bh >> 4, h = bh & 15;
    float* base = g_y + (size_t)b * Tn * Cn + h * Dn;

    const int tid = threadIdx.x;
    const int lane4 = tid & 15;     // float4 within the 64-channel group
    const int trow0 = tid >> 4;     // 16 t-rows in flight

    float s = 0.f;
    for (int t = trow0; t < Tn; t += 16) {
        float4 v = *(const float4*)(base + (size_t)t * Cn + lane4 * 4);
        s += (v.x + v.y) + (v.z + v.w);
    }
    red[tid] = s;
    __syncthreads();
    for (int off = 128; off > 0; off >>= 1) {
        if (tid < off) red[tid] += red[tid + off];
        __syncthreads();
    }
    if (tid == 0) s_mu = red[0] * (1.f / (float)(Tn * Dn));
    __syncthreads();
    const float mu = s_mu;

    float s2 = 0.f;
    for (int t = trow0; t < Tn; t += 16) {
        float4 v = *(const float4*)(base + (size_t)t * Cn + lane4 * 4);
        float dx = v.x - mu, dy = v.y - mu, dz = v.z - mu, dw = v.w - mu;
        s2 += (dx * dx + dy * dy) + (dz * dz + dw * dw);
    }
    red[tid] = s2;
    __syncthreads();
    for (int off = 128; off > 0; off >>= 1) {
        if (tid < off) red[tid] += red[tid + off];
        __syncthreads();
    }
    if (tid == 0) s_rstd = rsqrtf(red[0] * (1.f / (float)(Tn * Dn)) + 1e-5f);
    __syncthreads();
    const float rstd = s_rstd;

    float4 w4 = *(const float4*)(gn_w + h * Dn + lane4 * 4);
    float4 b4 = *(const float4*)(gn_b + h * Dn + lane4 * 4);
    for (int t = trow0; t < Tn; t += 16) {
        float* p = base + (size_t)t * Cn + lane4 * 4;
        float4 v = *(const float4*)p;
        v.x = (v.x - mu) * rstd * w4.x + b4.x;
        v.y = (v.y - mu) * rstd * w4.y + b4.y;
        v.z = (v.z - mu) * rstd * w4.z + b4.z;
        v.w = (v.w - mu) * rstd * w4.w + b4.w;
        *(float4*)p = v;
    }
}

// ---------------------------------------------------------------------------
// Launch: init table -> QKV GEMMs -> retention -> GN -> output GEMM.
// All on the capture stream; no syncs, no allocations.
// ---------------------------------------------------------------------------
extern "C" void kernel_launch(void* const* d_in, const int* in_sizes, int n_in,
                              void* d_out, int out_size) {
    (void)in_sizes; (void)n_in; (void)out_size;
    const float* x    = (const float*)d_in[0];
    const float* Wq   = (const float*)d_in[1];
    const float* Wk   = (const float*)d_in[2];
    const float* Wv   = (const float*)d_in[3];
    const float* Wo   = (const float*)d_in[4];
    const float* gn_w = (const float*)d_in[5];
    const float* gn_b = (const float*)d_in[6];
    float* out = (float*)d_out;

    init_ptab_kernel<<<Hn, 256>>>();
    gemm_qkv_kernel<<<dim3(Cn / 64, Mn / 128, 3), 256>>>(x, Wq, Wk, Wv);
    retention_kernel<<<dim3(Tn / 64, Bn * Hn), 256>>>();
    groupnorm_kernel<<<Bn * Hn, 256>>>(gn_w, gn_b);
    gemm_out_kernel<<<dim3(Cn / 64, Mn / 128), 256>>>(Wo, out);
}

// round 14
// speedup vs baseline: 1.6408x; 1.6408x over previous
#include <cuda_runtime.h>
#include <math.h>
#include <stdint.h>

// Shapes (fixed by the problem)
#define Bn 2
#define Tn 2048
#define Cn 1024
#define Hn 16
#define Dn 64
#define Mn (Bn * Tn)          // 4096 rows for all projections

// ---------------------------------------------------------------------------
// Scratch (device globals — no allocation allowed)
// ---------------------------------------------------------------------------
__device__ float g_q[(size_t)Bn * Hn * Tn * Dn];   // (B,H,T,D)
__device__ float g_k[(size_t)Bn * Hn * Tn * Dn];
__device__ float g_v[(size_t)Bn * Hn * Tn * Dn];
__device__ float g_y[(size_t)Bn * Tn * Cn];        // attn out, then GN'd in place
__device__ float g_ptab[Hn * Tn];                  // 0.125 * gamma_h^k
__device__ double g_gnpart[32][8][2];              // per-(bh, slice) {sum, sumsq}

// ---------------------------------------------------------------------------
// Helpers
// ---------------------------------------------------------------------------
__device__ __forceinline__ uint32_t f2tf32(float x) {
    uint32_t r;
    asm("cvt.rna.tf32.f32 %0, %1;" : "=r"(r) : "f"(x));
    return r;
}

__device__ __forceinline__ void mma_tf32(float c[4], const uint32_t a[4],
                                         const uint32_t b[2]) {
    asm volatile(
        "mma.sync.aligned.m16n8k8.row.col.f32.tf32.tf32.f32 "
        "{%0,%1,%2,%3}, {%4,%5,%6,%7}, {%8,%9}, {%0,%1,%2,%3};"
        : "+f"(c[0]), "+f"(c[1]), "+f"(c[2]), "+f"(c[3])
        : "r"(a[0]), "r"(a[1]), "r"(a[2]), "r"(a[3]), "r"(b[0]), "r"(b[1]));
}

// ---------------------------------------------------------------------------
// Decay table: ptab[h][k] = (1/sqrt(D)) * gamma_h^k, gamma_h = 1 - 2^(-5-h/2)
// ---------------------------------------------------------------------------
__global__ void init_ptab_kernel() {
    int h = blockIdx.x;
    double gamma = 1.0 - exp2(-5.0 - 0.5 * (double)h);
    double l2g = log2(gamma);
    for (int k = threadIdx.x; k < Tn; k += blockDim.x) {
        g_ptab[h * Tn + k] = (float)(0.125 * exp2(l2g * (double)k));
    }
}

// ---------------------------------------------------------------------------
// Tensor-core (mma.sync tf32) GEMM: C[m,n] = sum_k A[m,k] * W[n,k]
// BM=128, BN=128, BK=16, 256 threads = 8 warps (2 m x 4 n).
// Warp tile 64x32 = 4 mf (16 rows) x 4 nf (8 cols).   <-- mf MUST span 0..3
// Smem rows of 16 floats, XOR-swizzled in float4 units: u = r*4 + (c ^ ((r>>1)&3)).
// Fragment LDS pattern is conflict-free: bank = 16*(g&1) + perm4(g>>1)*4 + t.
// MODE 0: scatter into (B,H,T,D) head layout. MODE 1: plain row-major.
// ---------------------------------------------------------------------------
template <int MODE>
__device__ __forceinline__ void gemm_tc_impl(const float* __restrict__ A,
                                             const float* __restrict__ W,
                                             float* __restrict__ outp,
                                             int m0, int n0) {
    __shared__ float As[2][128 * 16];
    __shared__ float Bs[2][128 * 16];

    const int tid = threadIdx.x;
    const int wid = tid >> 5;
    const int lane = tid & 31;
    const int g = lane >> 2;          // groupID
    const int t = lane & 3;           // threadID_in_group
    const int sw = (g >> 1) & 3;      // fragment-row swizzle key ((r>>1)&3 == (g>>1)&3)
    const int warpM = (wid & 1) * 64;
    const int warpN = (wid >> 1) * 32;

    float acc[4][4][4];
#pragma unroll
    for (int mf = 0; mf < 4; mf++)
#pragma unroll
        for (int nf = 0; nf < 4; nf++)
#pragma unroll
            for (int q = 0; q < 4; q++) acc[mf][nf][q] = 0.f;

    // Staging geometry: r = tid>>2 (+64 for second half), c = tid&3.
    const int sr0 = tid >> 2;
    const int sc = tid & 3;

    float4 ra[2], rb[2];

    // Prologue: load k-tile 0
#pragma unroll
    for (int l = 0; l < 2; l++) {
        int r = sr0 + l * 64;
        ra[l] = *(const float4*)(A + (size_t)(m0 + r) * Cn + sc * 4);
        rb[l] = *(const float4*)(W + (size_t)(n0 + r) * Cn + sc * 4);
    }
#pragma unroll
    for (int l = 0; l < 2; l++) {
        int r = sr0 + l * 64;
        int u = r * 4 + (sc ^ ((r >> 1) & 3));
        *(uint4*)&As[0][u * 4] = make_uint4(f2tf32(ra[l].x), f2tf32(ra[l].y),
                                            f2tf32(ra[l].z), f2tf32(ra[l].w));
        *(uint4*)&Bs[0][u * 4] = make_uint4(f2tf32(rb[l].x), f2tf32(rb[l].y),
                                            f2tf32(rb[l].z), f2tf32(rb[l].w));
    }
    __syncthreads();

    for (int kt = 0; kt < Cn / 16; kt++) {
        const int cur = kt & 1;
        if (kt + 1 < Cn / 16) {
            const int k0 = (kt + 1) * 16;
#pragma unroll
            for (int l = 0; l < 2; l++) {
                int r = sr0 + l * 64;
                ra[l] = *(const float4*)(A + (size_t)(m0 + r) * Cn + k0 + sc * 4);
                rb[l] = *(const float4*)(W + (size_t)(n0 + r) * Cn + k0 + sc * 4);
            }
        }

        const float* Af = As[cur];
        const float* Bf = Bs[cur];
#pragma unroll
        for (int ks = 0; ks < 2; ks++) {
            const int c0 = ks * 2;
            const int u0 = (c0 ^ sw) * 4;
            const int u1 = ((c0 + 1) ^ sw) * 4;
            uint32_t afr[4][4];
#pragma unroll
            for (int mf = 0; mf < 4; mf++) {
                const float* p0 = Af + (warpM + 16 * mf + g) * 16 + t;
                const float* p8 = Af + (warpM + 16 * mf + g + 8) * 16 + t;
                afr[mf][0] = __float_as_uint(p0[u0]);
                afr[mf][1] = __float_as_uint(p8[u0]);
                afr[mf][2] = __float_as_uint(p0[u1]);
                afr[mf][3] = __float_as_uint(p8[u1]);
            }
            uint32_t bfr[4][2];
#pragma unroll
            for (int nf = 0; nf < 4; nf++) {
                const float* p = Bf + (warpN + 8 * nf + g) * 16 + t;
                bfr[nf][0] = __float_as_uint(p[u0]);
                bfr[nf][1] = __float_as_uint(p[u1]);
            }
#pragma unroll
            for (int mf = 0; mf < 4; mf++)
#pragma unroll
                for (int nf = 0; nf < 4; nf++)
                    mma_tf32(acc[mf][nf], afr[mf], bfr[nf]);
        }

        if (kt + 1 < Cn / 16) {
            const int nxt = cur ^ 1;
#pragma unroll
            for (int l = 0; l < 2; l++) {
                int r = sr0 + l * 64;
                int u = r * 4 + (sc ^ ((r >> 1) & 3));
                *(uint4*)&As[nxt][u * 4] =
                    make_uint4(f2tf32(ra[l].x), f2tf32(ra[l].y),
                               f2tf32(ra[l].z), f2tf32(ra[l].w));
                *(uint4*)&Bs[nxt][u * 4] =
                    make_uint4(f2tf32(rb[l].x), f2tf32(rb[l].y),
                               f2tf32(rb[l].z), f2tf32(rb[l].w));
            }
        }
        __syncthreads();
    }

    // Epilogue. C fragment: c0/c1 -> (g, 2t/2t+1), c2/c3 -> (g+8, same cols).
#pragma unroll
    for (int mf = 0; mf < 4; mf++) {
#pragma unroll
        for (int nf = 0; nf < 4; nf++) {
            const int m = m0 + warpM + 16 * mf + g;
            const int nb = n0 + warpN + 8 * nf;       // head-aligned base
            if (MODE == 0) {
                const int b = m >> 11;                 // T = 2048
                const int tr = m & (Tn - 1);
                const int h = nb >> 6;
                const int d = (nb & 63) + 2 * t;
                float* dst = outp + ((size_t)(b * Hn + h) * Tn + tr) * Dn + d;
                *(float2*)dst = make_float2(acc[mf][nf][0], acc[mf][nf][1]);
                *(float2*)(dst + 8 * (size_t)Dn) =
                    make_float2(acc[mf][nf][2], acc[mf][nf][3]);
            } else {
                float* dst = outp + (size_t)m * Cn + nb + 2 * t;
                *(float2*)dst = make_float2(acc[mf][nf][0], acc[mf][nf][1]);
                *(float2*)(dst + 8 * (size_t)Cn) =
                    make_float2(acc[mf][nf][2], acc[mf][nf][3]);
            }
        }
    }
}

__global__ __launch_bounds__(256, 2) void gemm_qkv_tc(const float* __restrict__ x,
                                                      const float* __restrict__ Wq,
                                                      const float* __restrict__ Wk,
                                                      const float* __restrict__ Wv) {
    const int z = blockIdx.z;
    const float* W = (z == 0) ? Wq : (z == 1) ? Wk : Wv;
    float* outp = (z == 0) ? g_q : (z == 1) ? g_k : g_v;
    gemm_tc_impl<0>(x, W, outp, blockIdx.y * 128, blockIdx.x * 128);
}

__global__ __launch_bounds__(256, 2) void gemm_out_tc(const float* __restrict__ Wo,
                                                      float* __restrict__ outp) {
    gemm_tc_impl<1>(g_y, Wo, outp, blockIdx.y * 128, blockIdx.x * 128);
}

// ---------------------------------------------------------------------------
// Retention attention (unchanged from R3 — validated; HMMA port next round).
// ---------------------------------------------------------------------------
__global__ __launch_bounds__(256) void retention_kernel() {
    __shared__ float Qs[64 * 64];
    __shared__ float KSs[64 * 64];
    __shared__ float Vs[64 * 64];

    const int bh = blockIdx.y;
    const int h = bh & (Hn - 1);
    const int b = bh >> 4;
    const int qt = (int)gridDim.x - 1 - (int)blockIdx.x;
    const int qbase = qt * 64;

    const float* __restrict__ Qg = g_q + (size_t)bh * Tn * Dn;
    const float* __restrict__ Kg = g_k + (size_t)bh * Tn * Dn;
    const float* __restrict__ Vg = g_v + (size_t)bh * Tn * Dn;
    const float* __restrict__ pt = g_ptab + h * Tn;

    const int tid = threadIdx.x;
    const int tx = tid & 15, ty = tid >> 4;
    const int i0 = ty * 4, j0 = tx * 4;

#pragma unroll
    for (int l = 0; l < 4; l++) {
        int f4 = tid + l * 256;
        int r = f4 >> 4, c4 = f4 & 15;
        *(float4*)&Qs[r * 64 + c4 * 4] =
            *(const float4*)(Qg + (size_t)(qbase + r) * Dn + c4 * 4);
    }

    float oacc[4][4];
#pragma unroll
    for (int a = 0; a < 4; a++)
#pragma unroll
        for (int c = 0; c < 4; c++) oacc[a][c] = 0.f;

    for (int kt = 0; kt <= qt; kt++) {
        const int kbase = kt * 64;
        __syncthreads();

#pragma unroll
        for (int l = 0; l < 4; l++) {
            int f4 = tid + l * 256;
            int r = f4 >> 4, c4 = f4 & 15;
            float4 kv = *(const float4*)(Kg + (size_t)(kbase + r) * Dn + c4 * 4);
            int d0 = c4 * 4;
            KSs[(d0 + 0) * 64 + (r ^ ((d0 + 0) & 60))] = kv.x;
            KSs[(d0 + 1) * 64 + (r ^ ((d0 + 1) & 60))] = kv.y;
            KSs[(d0 + 2) * 64 + (r ^ ((d0 + 2) & 60))] = kv.z;
            KSs[(d0 + 3) * 64 + (r ^ ((d0 + 3) & 60))] = kv.w;
            *(float4*)&Vs[r * 64 + c4 * 4] =
                *(const float4*)(Vg + (size_t)(kbase + r) * Dn + c4 * 4);
        }
        __syncthreads();

        float sacc[4][4];
#pragma unroll
        for (int a = 0; a < 4; a++)
#pragma unroll
            for (int c = 0; c < 4; c++) sacc[a][c] = 0.f;

#pragma unroll 16
        for (int d = 0; d < 64; d++) {
            float q0 = Qs[(i0 + 0) * 64 + d];
            float q1 = Qs[(i0 + 1) * 64 + d];
            float q2 = Qs[(i0 + 2) * 64 + d];
            float q3 = Qs[(i0 + 3) * 64 + d];
            float4 kk = *(const float4*)&KSs[d * 64 + (j0 ^ (d & 60))];
            sacc[0][0] = fmaf(q0, kk.x, sacc[0][0]); sacc[0][1] = fmaf(q0, kk.y, sacc[0][1]);
            sacc[0][2] = fmaf(q0, kk.z, sacc[0][2]); sacc[0][3] = fmaf(q0, kk.w, sacc[0][3]);
            sacc[1][0] = fmaf(q1, kk.x, sacc[1][0]); sacc[1][1] = fmaf(q1, kk.y, sacc[1][1]);
            sacc[1][2] = fmaf(q1, kk.z, sacc[1][2]); sacc[1][3] = fmaf(q1, kk.w, sacc[1][3]);
            sacc[2][0] = fmaf(q2, kk.x, sacc[2][0]); sacc[2][1] = fmaf(q2, kk.y, sacc[2][1]);
            sacc[2][2] = fmaf(q2, kk.z, sacc[2][2]); sacc[2][3] = fmaf(q2, kk.w, sacc[2][3]);
            sacc[3][0] = fmaf(q3, kk.x, sacc[3][0]); sacc[3][1] = fmaf(q3, kk.y, sacc[3][1]);
            sacc[3][2] = fmaf(q3, kk.z, sacc[3][2]); sacc[3][3] = fmaf(q3, kk.w, sacc[3][3]);
        }

        {
            const int dbase = qbase + i0 - kbase - j0;
            float pv[7];
#pragma unroll
            for (int e = 0; e < 7; e++) {
                int dd = dbase - 3 + e;
                pv[e] = (dd >= 0) ? pt[dd] : 0.f;
            }
#pragma unroll
            for (int a = 0; a < 4; a++)
#pragma unroll
                for (int c = 0; c < 4; c++)
                    sacc[a][c] *= pv[a - c + 3];
        }

        __syncthreads();
        float* Ss = KSs;
#pragma unroll
        for (int a = 0; a < 4; a++) {
            *(float4*)&Ss[(i0 + a) * 64 + j0] =
                make_float4(sacc[a][0], sacc[a][1], sacc[a][2], sacc[a][3]);
        }
        __syncthreads();

#pragma unroll 16
        for (int j = 0; j < 64; j++) {
            float s0 = Ss[(i0 + 0) * 64 + j];
            float s1 = Ss[(i0 + 1) * 64 + j];
            float s2 = Ss[(i0 + 2) * 64 + j];
            float s3 = Ss[(i0 + 3) * 64 + j];
            float4 vv = *(const float4*)&Vs[j * 64 + j0];
            oacc[0][0] = fmaf(s0, vv.x, oacc[0][0]); oacc[0][1] = fmaf(s0, vv.y, oacc[0][1]);
            oacc[0][2] = fmaf(s0, vv.z, oacc[0][2]); oacc[0][3] = fmaf(s0, vv.w, oacc[0][3]);
            oacc[1][0] = fmaf(s1, vv.x, oacc[1][0]); oacc[1][1] = fmaf(s1, vv.y, oacc[1][1]);
            oacc[1][2] = fmaf(s1, vv.z, oacc[1][2]); oacc[1][3] = fmaf(s1, vv.w, oacc[1][3]);
            oacc[2][0] = fmaf(s2, vv.x, oacc[2][0]); oacc[2][1] = fmaf(s2, vv.y, oacc[2][1]);
            oacc[2][2] = fmaf(s2, vv.z, oacc[2][2]); oacc[2][3] = fmaf(s2, vv.w, oacc[2][3]);
            oacc[3][0] = fmaf(s3, vv.x, oacc[3][0]); oacc[3][1] = fmaf(s3, vv.y, oacc[3][1]);
            oacc[3][2] = fmaf(s3, vv.z, oacc[3][2]); oacc[3][3] = fmaf(s3, vv.w, oacc[3][3]);
        }
    }

#pragma unroll
    for (int a = 0; a < 4; a++) {
        int t = qbase + i0 + a;
        *(float4*)(g_y + ((size_t)b * Tn + t) * Cn + h * Dn + j0) =
            make_float4(oacc[a][0], oacc[a][1], oacc[a][2], oacc[a][3]);
    }
}

// ---------------------------------------------------------------------------
// GroupNorm, deterministic 2-stage: fp64 partial sums per (bh, slice of 256 t),
// then normalize. 256 blocks per stage.
// ---------------------------------------------------------------------------
__global__ __launch_bounds__(256) void gn_part_kernel() {
    __shared__ double red[256], red2[256];
    const int slice = blockIdx.x;      // 0..7 (256 t-rows each)
    const int bh = blockIdx.y;         // 0..31
    const int b = bh >> 4, h = bh & 15;
    const float* base = g_y + (size_t)b * Tn * Cn + h * Dn;
    const int tid = threadIdx.x;
    const int lane4 = tid & 15, trow = tid >> 4;

    double s = 0.0, s2 = 0.0;
    for (int t = slice * 256 + trow; t < slice * 256 + 256; t += 16) {
        float4 v = *(const float4*)(base + (size_t)t * Cn + lane4 * 4);
        s += (double)v.x + (double)v.y + (double)v.z + (double)v.w;
        s2 += (double)v.x * v.x + (double)v.y * v.y +
              (double)v.z * v.z + (double)v.w * v.w;
    }
    red[tid] = s; red2[tid] = s2;
    __syncthreads();
    for (int off = 128; off > 0; off >>= 1) {
        if (tid < off) { red[tid] += red[tid + off]; red2[tid] += red2[tid + off]; }
        __syncthreads();
    }
    if (tid == 0) {
        g_gnpart[bh][slice][0] = red[0];
        g_gnpart[bh][slice][1] = red2[0];
    }
}

__global__ __launch_bounds__(256) void gn_apply_kernel(const float* __restrict__ gn_w,
                                                       const float* __restrict__ gn_b) {
    __shared__ float s_mu, s_rstd;
    const int slice = blockIdx.x;
    const int bh = blockIdx.y;
    const int b = bh >> 4, h = bh & 15;
    float* base = g_y + (size_t)b * Tn * Cn + h * Dn;
    const int tid = threadIdx.x;

    if (tid == 0) {
        double S = 0.0, S2 = 0.0;
        for (int s = 0; s < 8; s++) { S += g_gnpart[bh][s][0]; S2 += g_gnpart[bh][s][1]; }
        const double n = (double)Tn * (double)Dn;
        double mu = S / n;
        double var = S2 / n - mu * mu;
        s_mu = (float)mu;
        s_rstd = (float)(1.0 / sqrt(var + 1e-5));
    }
    __syncthreads();
    const float mu = s_mu, rstd = s_rstd;

    const int lane4 = tid & 15, trow = tid >> 4;
    float4 w4 = *(const float4*)(gn_w + h * Dn + lane4 * 4);
    float4 b4 = *(const float4*)(gn_b + h * Dn + lane4 * 4);
    for (int t = slice * 256 + trow; t < slice * 256 + 256; t += 16) {
        float* p = base + (size_t)t * Cn + lane4 * 4;
        float4 v = *(float4*)p;
        v.x = (v.x - mu) * rstd * w4.x + b4.x;
        v.y = (v.y - mu) * rstd * w4.y + b4.y;
        v.z = (v.z - mu) * rstd * w4.z + b4.z;
        v.w = (v.w - mu) * rstd * w4.w + b4.w;
        *(float4*)p = v;
    }
}

// ---------------------------------------------------------------------------
// Launch: ptab -> QKV (HMMA tf32) -> retention -> GN(2) -> out GEMM (HMMA tf32).
// ---------------------------------------------------------------------------
extern "C" void kernel_launch(void* const* d_in, const int* in_sizes, int n_in,
                              void* d_out, int out_size) {
    (void)in_sizes; (void)n_in; (void)out_size;
    const float* x    = (const float*)d_in[0];
    const float* Wq   = (const float*)d_in[1];
    const float* Wk   = (const float*)d_in[2];
    const float* Wv   = (const float*)d_in[3];
    const float* Wo   = (const float*)d_in[4];
    const float* gn_w = (const float*)d_in[5];
    const float* gn_b = (const float*)d_in[6];
    float* out = (float*)d_out;

    init_ptab_kernel<<<Hn, 256>>>();
    gemm_qkv_tc<<<dim3(Cn / 128, Mn / 128, 3), 256>>>(x, Wq, Wk, Wv);
    retention_kernel<<<dim3(Tn / 64, Bn * Hn), 256>>>();
    gn_part_kernel<<<dim3(8, Bn * Hn), 256>>>();
    gn_apply_kernel<<<dim3(8, Bn * Hn), 256>>>(gn_w, gn_b);
    gemm_out_tc<<<dim3(Cn / 128, Mn / 128), 256>>>(Wo, out);
}